// round 11
// baseline (speedup 1.0000x reference)
#include <cuda_runtime.h>
#include <math.h>

#define Bdim 4
#define Ndim 48
#define Rdim 16
#define Tdim 33
#define NCdim 80
#define NIdim 5
#define NN (Ndim * Ndim)          // 2304
#define NEGV -1000.0f
#define PREP_ROWS 32
#define HR 12                     // rows per dp CTA (quarter split)
#define PITCH 49                  // padded pitch: conflict-free row-major LDS.32

// g_M[b,t][u*48+v] = trans[b,u,v,t]
__device__ float g_M[Bdim * Tdim * NN];
// scratch: exp(path score) per [b, c, xy]
__device__ float g_scratch[Bdim * NCdim * NN];

// ---------------------------------------------------------------------------
// Kernel 0: streaming transpose [B*2304, 33] -> per-t rows.
__global__ __launch_bounds__(256) void prep_kernel(const float* __restrict__ trans)
{
    __shared__ float tile[PREP_ROWS * Tdim];   // 1056 floats

    const int chunk = blockIdx.x;              // 0..71
    const int b     = blockIdx.y;
    const int tid   = threadIdx.x;
    const int row0  = chunk * PREP_ROWS;

    const float* src = trans + ((size_t)b * NN + row0) * Tdim;
    #pragma unroll
    for (int i = tid; i < PREP_ROWS * Tdim; i += 256)
        tile[i] = __ldg(src + i);              // fully coalesced
    __syncthreads();

    float* dst = g_M + (size_t)b * Tdim * NN + row0;
    #pragma unroll
    for (int i = tid; i < PREP_ROWS * Tdim; i += 256) {
        const int t = i >> 5;                  // /32
        const int r = i & 31;
        dst[(size_t)t * NN + r] = tile[r * Tdim + t];   // stride-33 smem: conflict-free
    }
}

// ---------------------------------------------------------------------------
// Dummy kernel: phase-shifts the ncu -s5 -c1 capture onto dp_kernel.
__global__ void dummy_kernel() {}

// ---------------------------------------------------------------------------
// Kernel 1: one CTA per (c, b, row-quarter). 144 threads: thread = (cq, xr),
// cq = column quad (0..11, warp-broadcast B reads), xr = local row (0..11,
// conflict-free pitch-49 A reads). 4 outputs per thread per stage.
__global__ __launch_bounds__(144) void dp_kernel(const int* __restrict__ rules)
{
    __shared__ float A0[HR * PITCH];           // hop0 slice (pitch 49), then S slice
    __shared__ float B1[NN];                   // hop1 (full)
    __shared__ float B2[NN];                   // hop2 (full)

    const int c = blockIdx.x;
    const int b = blockIdx.y;
    const int rowbase = blockIdx.z * HR;

    const int tid = threadIdx.x;
    const int xr  = tid % HR;                  // 0..11
    const int cq  = tid / HR;                  // 0..11
    const int col0 = cq * 4;

    const int r0 = __ldg(rules + c * 3 + 0);
    const int r1 = __ldg(rules + c * 3 + 1);
    const int r2 = __ldg(rules + c * 3 + 2);

    const float*  h0 = g_M + (size_t)(b * Tdim + r0) * NN + rowbase * Ndim;
    const float4* h1 = (const float4*)(g_M + (size_t)(b * Tdim + r1) * NN);
    const float4* h2 = (const float4*)(g_M + (size_t)(b * Tdim + r2) * NN);

    // fills: B1/B2 full (float4, coalesced), hop0 slice (12x48) into pitch-49 A0
    float4* B14 = (float4*)B1;
    float4* B24 = (float4*)B2;
    #pragma unroll
    for (int j = 0; j < 4; j++) {
        B14[tid + j * 144] = h1[tid + j * 144];
        B24[tid + j * 144] = h2[tid + j * 144];
    }
    #pragma unroll
    for (int i = tid; i < HR * Ndim; i += 144) {
        const int u = i / Ndim;
        const int v = i - u * Ndim;
        A0[u * PITCH + v] = h0[i];             // coalesced gmem read
    }
    __syncthreads();

    float a0, a1, a2, a3;
    a0 = a1 = a2 = a3 = -INFINITY;

    const float* ap  = A0 + xr * PITCH;
    const float* bp1 = B1 + col0;

    // ---- stage 1: S[x][col0..+3] = max_k hop0[x][k] + hop1[k][..] ----
    #pragma unroll 8
    for (int k = 0; k < Ndim; k++) {
        const float  av = ap[k];                             // conflict-free
        const float4 bv = *(const float4*)(bp1 + k * Ndim);  // warp-broadcast
        a0 = fmaxf(a0, av + bv.x);
        a1 = fmaxf(a1, av + bv.y);
        a2 = fmaxf(a2, av + bv.z);
        a3 = fmaxf(a3, av + bv.w);
    }
    __syncthreads();                           // all A0 reads done

    // write S slice into A0 (same pitch-49 layout)
    {
        float* sp = A0 + xr * PITCH + col0;
        sp[0] = a0; sp[1] = a1; sp[2] = a2; sp[3] = a3;
    }
    __syncthreads();

    // ---- stage 2: out[x][col0..+3] = exp(max_k S[x][k] + hop2[k][..]) ----
    a0 = a1 = a2 = a3 = -INFINITY;
    const float* bp2 = B2 + col0;

    #pragma unroll 8
    for (int k = 0; k < Ndim; k++) {
        const float  av = ap[k];                             // S row, conflict-free
        const float4 bv = *(const float4*)(bp2 + k * Ndim);  // warp-broadcast
        a0 = fmaxf(a0, av + bv.x);
        a1 = fmaxf(a1, av + bv.y);
        a2 = fmaxf(a2, av + bv.z);
        a3 = fmaxf(a3, av + bv.w);
    }

    float* op = g_scratch + ((size_t)b * NCdim + c) * NN + (rowbase + xr) * Ndim + col0;
    *(float4*)op = make_float4(__expf(a0), __expf(a1), __expf(a2), __expf(a3));
}

// ---------------------------------------------------------------------------
// Kernel 2: one thread per (b, xy, group-of-4 triples). 20 coalesced chain
// loads per thread, int4 mask load + float4 store.
__global__ __launch_bounds__(256) void combine_kernel(const int*   __restrict__ type_mask,
                                                      const float* __restrict__ weights,
                                                      const float* __restrict__ biases,
                                                      float*       __restrict__ out)
{
    __shared__ float ws[NCdim];
    __shared__ float bs[Rdim];
    const int tid = threadIdx.x;
    if (tid < NCdim) ws[tid] = weights[tid];
    if (tid < Rdim)  bs[tid] = biases[tid];
    __syncthreads();

    const int idx = blockIdx.x * 256 + tid;   // 0 .. B*NN*4-1 (36864)
    const int g   = idx & 3;
    const int bxy = idx >> 2;
    const int xy  = bxy % NN;
    const int b   = bxy / NN;

    float acc0 = bs[g * 4 + 0];
    float acc1 = bs[g * 4 + 1];
    float acc2 = bs[g * 4 + 2];
    float acc3 = bs[g * 4 + 3];

    const float* sp = g_scratch + ((size_t)b * NCdim + g * 20) * NN + xy;
    const float* wp = ws + g * 20;
    #pragma unroll
    for (int j = 0; j < 5; j++) {
        acc0 = fmaf(sp[(j +  0) * NN], wp[j +  0], acc0);
        acc1 = fmaf(sp[(j +  5) * NN], wp[j +  5], acc1);
        acc2 = fmaf(sp[(j + 10) * NN], wp[j + 10], acc2);
        acc3 = fmaf(sp[(j + 15) * NN], wp[j + 15], acc3);
    }

    const int4 m = *(const int4*)(type_mask + (size_t)bxy * Rdim + g * 4);
    float4 o;
    o.x = (m.x == 0) ? acc0 : NEGV;
    o.y = (m.y == 0) ? acc1 : NEGV;
    o.z = (m.z == 0) ? acc2 : NEGV;
    o.w = (m.w == 0) ? acc3 : NEGV;
    *(float4*)(out + (size_t)bxy * Rdim + g * 4) = o;
}

extern "C" void kernel_launch(void* const* d_in, const int* in_sizes, int n_in,
                              void* d_out, int out_size)
{
    const float* transitions = (const float*)d_in[0];
    const int*   type_mask   = (const int*)  d_in[1];
    const int*   rules       = (const int*)  d_in[2];
    const float* weights     = (const float*)d_in[3];
    const float* biases      = (const float*)d_in[4];
    float* out = (float*)d_out;

    dim3 grid0(NN / PREP_ROWS, Bdim);          // (72, 4) = 288 CTAs
    prep_kernel<<<grid0, 256>>>(transitions);

    dummy_kernel<<<1, 32>>>();                 // ncu capture phase shift -> dp

    dim3 grid1(NCdim, Bdim, Ndim / HR);        // (80, 4, 4) = 1280 CTAs
    dp_kernel<<<grid1, 144>>>(rules);

    combine_kernel<<<(Bdim * NN * 4) / 256, 256>>>(type_mask, weights, biases, out);
}

// round 12
// speedup vs baseline: 1.2166x; 1.2166x over previous
#include <cuda_runtime.h>
#include <math.h>

#define Bdim 4
#define Ndim 48
#define Rdim 16
#define Tdim 33
#define NCdim 80
#define NIdim 5
#define NN (Ndim * Ndim)          // 2304
#define NEGV -1000.0f
#define PREP_ROWS 32
#define HROWS 24                  // rows per dp CTA (half split)
#define PITCH 49                  // padded pitch: conflict-free row-major LDS.32

// g_M[b,t][u*48+v] = trans[b,u,v,t]
__device__ float g_M[Bdim * Tdim * NN];
// scratch: exp(path score) per [b, c, xy]
__device__ float g_scratch[Bdim * NCdim * NN];

// ---------------------------------------------------------------------------
// Kernel 0: streaming transpose [B*2304, 33] -> per-t rows.
__global__ __launch_bounds__(256) void prep_kernel(const float* __restrict__ trans)
{
    __shared__ float tile[PREP_ROWS * Tdim];   // 1056 floats

    const int chunk = blockIdx.x;              // 0..71
    const int b     = blockIdx.y;
    const int tid   = threadIdx.x;
    const int row0  = chunk * PREP_ROWS;

    const float* src = trans + ((size_t)b * NN + row0) * Tdim;
    #pragma unroll
    for (int i = tid; i < PREP_ROWS * Tdim; i += 256)
        tile[i] = __ldg(src + i);              // fully coalesced
    __syncthreads();

    float* dst = g_M + (size_t)b * Tdim * NN + row0;
    #pragma unroll
    for (int i = tid; i < PREP_ROWS * Tdim; i += 256) {
        const int t = i >> 5;                  // /32
        const int r = i & 31;
        dst[(size_t)t * NN + r] = tile[r * Tdim + t];   // stride-33 smem: conflict-free
    }
}

// ---------------------------------------------------------------------------
// Kernel 1: one CTA per (c, b, row-half). 144 threads: thread = (oct, xr),
// oct = column octet (0..5, warp-broadcast B reads), xr = local row (0..23,
// conflict-free pitch-49 A reads). 8 outputs per thread per stage.
__global__ __launch_bounds__(144) void dp_kernel(const int* __restrict__ rules)
{
    __shared__ float A0[HROWS * PITCH];        // hop0 slice (pitch 49), then S
    __shared__ float B1[NN];                   // hop1 (full)
    __shared__ float B2[NN];                   // hop2 (full)

    const int c = blockIdx.x;
    const int b = blockIdx.y;
    const int rowbase = blockIdx.z * HROWS;

    const int tid = threadIdx.x;
    const int oct = tid / HROWS;               // 0..5
    const int xr  = tid - oct * HROWS;         // 0..23

    const int r0 = __ldg(rules + c * 3 + 0);
    const int r1 = __ldg(rules + c * 3 + 1);
    const int r2 = __ldg(rules + c * 3 + 2);

    const float*  h0 = g_M + (size_t)(b * Tdim + r0) * NN + rowbase * Ndim;
    const float4* h1 = (const float4*)(g_M + (size_t)(b * Tdim + r1) * NN);
    const float4* h2 = (const float4*)(g_M + (size_t)(b * Tdim + r2) * NN);

    // fills: B1/B2 full (float4, coalesced), hop0 slice into pitch-49 A0
    float4* B14 = (float4*)B1;
    float4* B24 = (float4*)B2;
    #pragma unroll
    for (int j = 0; j < 4; j++) {
        B14[tid + j * 144] = h1[tid + j * 144];
        B24[tid + j * 144] = h2[tid + j * 144];
    }
    #pragma unroll
    for (int i = tid; i < HROWS * Ndim; i += 144) {
        const int u = i / Ndim;
        const int v = i - u * Ndim;
        A0[u * PITCH + v] = h0[i];             // coalesced gmem read
    }
    __syncthreads();

    float a0, a1, a2, a3, a4, a5, a6, a7;
    a0 = a1 = a2 = a3 = a4 = a5 = a6 = a7 = -INFINITY;

    const float* ap  = A0 + xr * PITCH;
    const float* bp1 = B1 + oct * 8;

    // ---- stage 1: S[x][oct*8..+7] = max_k hop0[x][k] + hop1[k][..] ----
    #pragma unroll 8
    for (int k = 0; k < Ndim; k++) {
        const float  av  = ap[k];                              // conflict-free
        const float4 bv0 = *(const float4*)(bp1 + k * Ndim);   // warp-broadcast
        const float4 bv1 = *(const float4*)(bp1 + k * Ndim + 4);
        a0 = fmaxf(a0, av + bv0.x); a1 = fmaxf(a1, av + bv0.y);
        a2 = fmaxf(a2, av + bv0.z); a3 = fmaxf(a3, av + bv0.w);
        a4 = fmaxf(a4, av + bv1.x); a5 = fmaxf(a5, av + bv1.y);
        a6 = fmaxf(a6, av + bv1.z); a7 = fmaxf(a7, av + bv1.w);
    }
    __syncthreads();                           // all A0 reads done

    // write S into A0 (same pitch-49 layout)
    {
        float* sp = A0 + xr * PITCH + oct * 8;
        sp[0] = a0; sp[1] = a1; sp[2] = a2; sp[3] = a3;
        sp[4] = a4; sp[5] = a5; sp[6] = a6; sp[7] = a7;
    }
    __syncthreads();

    // ---- stage 2: out[x][oct*8..+7] = exp(max_k S[x][k] + hop2[k][..]) ----
    a0 = a1 = a2 = a3 = a4 = a5 = a6 = a7 = -INFINITY;
    const float* bp2 = B2 + oct * 8;

    #pragma unroll 8
    for (int k = 0; k < Ndim; k++) {
        const float  av  = ap[k];                              // S row, conflict-free
        const float4 bv0 = *(const float4*)(bp2 + k * Ndim);   // warp-broadcast
        const float4 bv1 = *(const float4*)(bp2 + k * Ndim + 4);
        a0 = fmaxf(a0, av + bv0.x); a1 = fmaxf(a1, av + bv0.y);
        a2 = fmaxf(a2, av + bv0.z); a3 = fmaxf(a3, av + bv0.w);
        a4 = fmaxf(a4, av + bv1.x); a5 = fmaxf(a5, av + bv1.y);
        a6 = fmaxf(a6, av + bv1.z); a7 = fmaxf(a7, av + bv1.w);
    }

    float* op = g_scratch + ((size_t)b * NCdim + c) * NN + (rowbase + xr) * Ndim + oct * 8;
    *(float4*)(op + 0) = make_float4(__expf(a0), __expf(a1), __expf(a2), __expf(a3));
    *(float4*)(op + 4) = make_float4(__expf(a4), __expf(a5), __expf(a6), __expf(a7));
}

// ---------------------------------------------------------------------------
// Kernel 2: one thread per (b, xy, t). 147456 threads -> ~32 warps/SM.
// 5 scratch loads (MLP=5), coalesced scalar mask load + store.
__global__ __launch_bounds__(256) void combine_kernel(const int*   __restrict__ type_mask,
                                                      const float* __restrict__ weights,
                                                      const float* __restrict__ biases,
                                                      float*       __restrict__ out)
{
    __shared__ float ws[NCdim];
    __shared__ float bs[Rdim];
    const int tid = threadIdx.x;
    if (tid < NCdim) ws[tid] = weights[tid];
    if (tid < Rdim)  bs[tid] = biases[tid];
    __syncthreads();

    const int idx = blockIdx.x * 256 + tid;   // 0 .. B*NN*16-1 (147456)
    const int t   = idx & 15;
    const int bxy = idx >> 4;
    const int xy  = bxy % NN;
    const int b   = bxy / NN;

    const float* sp = g_scratch + ((size_t)b * NCdim + t * NIdim) * NN + xy;
    const float* wp = ws + t * NIdim;

    float acc = bs[t];
    #pragma unroll
    for (int i = 0; i < NIdim; i++)
        acc = fmaf(sp[(size_t)i * NN], wp[i], acc);

    const int m = type_mask[idx];
    out[idx] = (m == 0) ? acc : NEGV;
}

extern "C" void kernel_launch(void* const* d_in, const int* in_sizes, int n_in,
                              void* d_out, int out_size)
{
    const float* transitions = (const float*)d_in[0];
    const int*   type_mask   = (const int*)  d_in[1];
    const int*   rules       = (const int*)  d_in[2];
    const float* weights     = (const float*)d_in[3];
    const float* biases      = (const float*)d_in[4];
    float* out = (float*)d_out;

    dim3 grid0(NN / PREP_ROWS, Bdim);          // (72, 4) = 288 CTAs
    prep_kernel<<<grid0, 256>>>(transitions);

    dim3 grid1(NCdim, Bdim, Ndim / HROWS);     // (80, 4, 2) = 640 CTAs
    dp_kernel<<<grid1, 144>>>(rules);

    combine_kernel<<<(Bdim * NN * Rdim) / 256, 256>>>(type_mask, weights, biases, out);
}